// round 2
// baseline (speedup 1.0000x reference)
#include <cuda_runtime.h>
#include <math.h>

// Problem geometry
#define NDIR   1986
#define NV     64
#define NBP    128     // B*P = 8*16
#define TPB    128
#define NCHUNK 16      // 16*128 = 2048 >= 1986

// Output layout (float element offsets inside d_out)
#define OFF_POINTS 0
#define OFF_DH     762624      // + 128*1986*4
#define OFF_OVER   1779456     // + 128
#define OFF_MEAN   1779584     // + 384
#define OFF_DIRS   1779968     // + 5958
#define OFF_LV     1785926     // + 24576 -> 1810502 total

__device__ float g_dirs[NDIR * 3];
__device__ float g_localv[NBP * NV * 3];
__device__ float g_mean[NBP * 3];

__constant__ float c_pow10[21] = {
    1e0f, 1e1f, 1e2f, 1e3f, 1e4f, 1e5f, 1e6f, 1e7f, 1e8f, 1e9f, 1e10f,
    1e11f, 1e12f, 1e13f, 1e14f, 1e15f, 1e16f, 1e17f, 1e18f, 1e19f, 1e20f
};

// ---------------------------------------------------------------------------
// Directions: match numpy float64 linspace + trig, cast to float32.
// th1 = linspace(-pi/2, pi/2, 33), th2 = linspace(-pi, pi, 65)
// main block: i in [1,31], j in [0,63], idx = (i-1)*64 + j
// poles: idx 1984 -> (th1[0],  th2[0]);  idx 1985 -> (th1[32], th2[0])
// ---------------------------------------------------------------------------
__global__ void dirs_kernel(float* __restrict__ out) {
    int d = blockIdx.x * blockDim.x + threadIdx.x;
    if (d >= NDIR) return;

    const double PI = 3.14159265358979323846;
    const double STEP = PI / 32.0;   // both linspace steps equal pi/32 exactly

    double th1, th2;
    if (d < 1984) {
        int i = d / 64 + 1;
        int j = d % 64;
        th1 = __dadd_rn(__dmul_rn((double)i, STEP), -PI / 2.0);
        th2 = __dadd_rn(__dmul_rn((double)j, STEP), -PI);
    } else {
        th1 = (d == 1984) ? (-PI / 2.0) : (PI / 2.0);  // numpy endpoint exact
        th2 = -PI;
    }

    double s1, c1, s2, c2;
    sincos(th1, &s1, &c1);
    sincos(th2, &s2, &c2);

    float dx = (float)(c1 * c2);
    float dy = (float)(c1 * s2);
    float dz = (float)s1;

    g_dirs[3 * d + 0] = dx;
    g_dirs[3 * d + 1] = dy;
    g_dirs[3 * d + 2] = dz;
    out[OFF_DIRS + 3 * d + 0] = dx;
    out[OFF_DIRS + 3 * d + 1] = dy;
    out[OFF_DIRS + 3 * d + 2] = dz;
}

// ---------------------------------------------------------------------------
// Per-(b,p): mean over 64 vertices, local_v, overlap zeros.
// 128 blocks x 64 threads (1 thread per vertex).
// ---------------------------------------------------------------------------
__global__ void setup_kernel(const float* __restrict__ verts,
                             float* __restrict__ out) {
    int bp = blockIdx.x;
    int v  = threadIdx.x;

    float px = verts[(bp * NV + v) * 3 + 0];
    float py = verts[(bp * NV + v) * 3 + 1];
    float pz = verts[(bp * NV + v) * 3 + 2];

    float sx = px, sy = py, sz = pz;
    #pragma unroll
    for (int o = 16; o > 0; o >>= 1) {
        sx += __shfl_down_sync(0xffffffffu, sx, o);
        sy += __shfl_down_sync(0xffffffffu, sy, o);
        sz += __shfl_down_sync(0xffffffffu, sz, o);
    }

    __shared__ float sred[6];
    __shared__ float smean[3];
    int warp = v >> 5, lane = v & 31;
    if (lane == 0) {
        sred[warp * 3 + 0] = sx;
        sred[warp * 3 + 1] = sy;
        sred[warp * 3 + 2] = sz;
    }
    __syncthreads();
    if (v == 0) {
        float mx = (sred[0] + sred[3]) * (1.0f / 64.0f);
        float my = (sred[1] + sred[4]) * (1.0f / 64.0f);
        float mz = (sred[2] + sred[5]) * (1.0f / 64.0f);
        smean[0] = mx; smean[1] = my; smean[2] = mz;
        g_mean[bp * 3 + 0] = mx;
        g_mean[bp * 3 + 1] = my;
        g_mean[bp * 3 + 2] = mz;
        out[OFF_MEAN + bp * 3 + 0] = mx;
        out[OFF_MEAN + bp * 3 + 1] = my;
        out[OFF_MEAN + bp * 3 + 2] = mz;
        out[OFF_OVER + bp] = 0.0f;
    }
    __syncthreads();

    float lx = px - smean[0];
    float ly = py - smean[1];
    float lz = pz - smean[2];
    int idx = (bp * NV + v) * 3;
    g_localv[idx + 0] = lx;
    g_localv[idx + 1] = ly;
    g_localv[idx + 2] = lz;
    out[OFF_LV + idx + 0] = lx;
    out[OFF_LV + idx + 1] = ly;
    out[OFF_LV + idx + 2] = lz;
}

// ---------------------------------------------------------------------------
// Main: grid (NCHUNK, NBP), 128 threads; one thread = one direction.
//   pass1: z = local_v . dir, zm = max(z,0) -> smem cache + running max
//   k from underflow guard (ceil of log10 deficit), pow10 const table
//   pass2: l = log2(zm*k) (cache in smem), sum of clip(zms^p)
//   h = clip(sum^(1/p)); pass3: dhdz = clip(exp2((p-1)(l - log2 h))) -> surf
// ---------------------------------------------------------------------------
__global__ __launch_bounds__(TPB)
void main_kernel(const float* __restrict__ smooth, float* __restrict__ out) {
    __shared__ float4 slv[NV];           // local_v padded to float4
    __shared__ float  scache[NV * TPB];  // zm, then log2(zms)

    const int bp  = blockIdx.y;
    const int tid = threadIdx.x;
    const int d   = blockIdx.x * TPB + tid;

    if (tid < NV) {
        const float* lv = &g_localv[(bp * NV + tid) * 3];
        slv[tid] = make_float4(lv[0], lv[1], lv[2], 0.0f);
    }
    __syncthreads();

    if (d >= NDIR) return;   // no further barriers below

    const float dx = g_dirs[3 * d + 0];
    const float dy = g_dirs[3 * d + 1];
    const float dz = g_dirs[3 * d + 2];
    const float p  = smooth[bp];

    // ---- pass 1: zm and max ----
    float zmax = 0.0f;
    #pragma unroll 8
    for (int v = 0; v < NV; v++) {
        float4 lv = slv[v];
        float z = fmaf(lv.x, dx, fmaf(lv.y, dy, lv.z * dz));
        z = fmaxf(z, 0.0f);
        scache[v * TPB + tid] = z;
        zmax = fmaxf(zmax, z);
    }

    // ---- scale factor k ----
    float zlog  = log10f(zmax);                 // -inf if zmax == 0
    float expo  = zlog * p;
    float lk    = (expo < -20.0f) ? ((-20.0f - expo) / p) : 0.0f;
    float kexp  = ceilf(lk);
    kexp = fminf(fmaxf(kexp, 0.0f), 20.0f);     // +inf -> 20
    const float k = c_pow10[(int)kexp];

    // ---- pass 2: l = log2(zms); sum of clip(zms^p) ----
    float sum = 0.0f;
    #pragma unroll 8
    for (int v = 0; v < NV; v++) {
        float zm  = scache[v * TPB + tid];
        float zms = zm * k;
        float l   = __log2f(zms);               // -inf when zms == 0
        scache[v * TPB + tid] = l;
        float zp = exp2f(p * l);
        zp = fminf(fmaxf(zp, 1e-20f), 1e20f);
        if (!(zms > 0.0f)) zp = 0.0f;
        sum += zp;
    }

    // ---- h ----
    float h = exp2f(__log2f(sum) * (1.0f / p)); // 0 if sum == 0
    h = fminf(fmaxf(h, 1e-20f), 1e20f);
    const float log2h = __log2f(h);             // finite (h clamped)
    const float pm1   = p - 1.0f;
    const float cc    = -pm1 * log2h;

    // ---- pass 3: dhdz, surf accumulation ----
    float sxv = 0.0f, syv = 0.0f, szv = 0.0f;
    #pragma unroll 8
    for (int v = 0; v < NV; v++) {
        float l  = scache[v * TPB + tid];
        float dh = exp2f(fmaf(pm1, l, cc));     // l=-inf -> 0 -> clamp LB
        dh = fminf(fmaxf(dh, 1e-20f), 1e20f);
        float4 lv = slv[v];
        sxv = fmaf(dh, lv.x, sxv);
        syv = fmaf(dh, lv.y, syv);
        szv = fmaf(dh, lv.z, szv);
    }

    const float mx = g_mean[bp * 3 + 0];
    const float my = g_mean[bp * 3 + 1];
    const float mz = g_mean[bp * 3 + 2];

    size_t pidx = ((size_t)bp * NDIR + d) * 3;
    out[OFF_POINTS + pidx + 0] = sxv + mx;
    out[OFF_POINTS + pidx + 1] = syv + my;
    out[OFF_POINTS + pidx + 2] = szv + mz;

    float hout = h / k;                         // clip(-1e20,1e20): already in range
    float4 dh4 = make_float4(dx, dy, dz, hout);
    ((float4*)(out + OFF_DH))[(size_t)bp * NDIR + d] = dh4;
}

// ---------------------------------------------------------------------------
extern "C" void kernel_launch(void* const* d_in, const int* in_sizes, int n_in,
                              void* d_out, int out_size) {
    const float* verts  = (const float*)d_in[0];
    const float* smooth = (const float*)d_in[1];
    float* out = (float*)d_out;

    dirs_kernel<<<NCHUNK, TPB>>>(out);
    setup_kernel<<<NBP, NV>>>(verts, out);
    main_kernel<<<dim3(NCHUNK, NBP), TPB>>>(smooth, out);
}

// round 3
// speedup vs baseline: 1.3372x; 1.3372x over previous
#include <cuda_runtime.h>
#include <math.h>

// Problem geometry
#define NDIR   1986
#define NV     64
#define NBP    128     // B*P = 8*16
#define TPB    128
#define NCHUNK 16      // 16*128 = 2048 >= 1986

// Output layout (float element offsets inside d_out)
#define OFF_POINTS 0
#define OFF_DH     762624      // + 128*1986*4
#define OFF_OVER   1779456     // + 128
#define OFF_MEAN   1779584     // + 384
#define OFF_DIRS   1779968     // + 5958
#define OFF_LV     1785926     // + 24576 -> 1810502 total

__constant__ float c_pow10[21] = {
    1e0f, 1e1f, 1e2f, 1e3f, 1e4f, 1e5f, 1e6f, 1e7f, 1e8f, 1e9f, 1e10f,
    1e11f, 1e12f, 1e13f, 1e14f, 1e15f, 1e16f, 1e17f, 1e18f, 1e19f, 1e20f
};

// Special f64->f32-cast trig values (catastrophic-cancellation angles):
//   cos(pi/2)  [f64] -> 6.123233995736766e-17
//   sin(-pi)   [f64] -> -1.2246467991473532e-16
#define COS_HALFPI  6.123234e-17f
#define SIN_NEGPI  -1.2246468e-16f

// ---------------------------------------------------------------------------
// Single fused kernel. Grid (NCHUNK, NBP), 128 threads.
// One thread = one direction of one (b,p) tile.
//   prologue: block loads its 64 vertices, reduces mean, builds local_v in smem
//   per-thread direction from f32 sincos (special angles hardcoded)
//   pass1: zmax over v (z recomputed, nothing cached)
//   k underflow-guard scale
//   pass2 (fused): w = zms^(p-1) [1 lg2 + 1 ex2], zp = clip(w*zms),
//                  sum += zp, (wx,wy,wz) += w*lv
//   epilogue: h = clip(sum^(1/p)); surf = (wx..)*h^(1-p) + mean
// ---------------------------------------------------------------------------
__global__ __launch_bounds__(TPB)
void fused_kernel(const float* __restrict__ verts,
                  const float* __restrict__ smooth,
                  float* __restrict__ out) {
    __shared__ float4 slv[NV];
    __shared__ float  sred[6];
    __shared__ float  smean[3];

    const int bp  = blockIdx.y;
    const int tid = threadIdx.x;
    const int d   = blockIdx.x * TPB + tid;

    // ---- prologue: mean + local_v ----
    float px = 0.f, py = 0.f, pz = 0.f;
    if (tid < NV) {
        const float* vp = verts + (bp * NV + tid) * 3;
        px = vp[0]; py = vp[1]; pz = vp[2];
    }
    {
        float sx = px, sy = py, sz = pz;
        #pragma unroll
        for (int o = 16; o > 0; o >>= 1) {
            sx += __shfl_down_sync(0xffffffffu, sx, o);
            sy += __shfl_down_sync(0xffffffffu, sy, o);
            sz += __shfl_down_sync(0xffffffffu, sz, o);
        }
        int warp = tid >> 5, lane = tid & 31;
        if (warp < 2 && lane == 0) {
            sred[warp * 3 + 0] = sx;
            sred[warp * 3 + 1] = sy;
            sred[warp * 3 + 2] = sz;
        }
    }
    __syncthreads();
    if (tid == 0) {
        smean[0] = (sred[0] + sred[3]) * (1.0f / 64.0f);
        smean[1] = (sred[1] + sred[4]) * (1.0f / 64.0f);
        smean[2] = (sred[2] + sred[5]) * (1.0f / 64.0f);
    }
    __syncthreads();
    const float mx = smean[0], my = smean[1], mz = smean[2];
    if (tid < NV) {
        slv[tid] = make_float4(px - mx, py - my, pz - mz, 0.0f);
    }
    __syncthreads();

    // ---- aux outputs (block x==0 owns per-bp tensors) ----
    if (blockIdx.x == 0) {
        if (tid == 0) {
            out[OFF_MEAN + bp * 3 + 0] = mx;
            out[OFF_MEAN + bp * 3 + 1] = my;
            out[OFF_MEAN + bp * 3 + 2] = mz;
            out[OFF_OVER + bp] = 0.0f;
        }
        if (tid < NV) {
            float4 lv = slv[tid];
            int idx = OFF_LV + (bp * NV + tid) * 3;
            out[idx + 0] = lv.x;
            out[idx + 1] = lv.y;
            out[idx + 2] = lv.z;
        }
    }

    if (d >= NDIR) return;   // no barriers below this point

    // ---- direction ----
    const float STEP  = 0.09817477042468103f;   // pi/32
    const float NPI   = -3.14159265358979323846f;
    const float NPI2  = -1.57079632679489662f;
    float c1, s1, c2, s2;
    if (d >= 1984) {
        c1 = COS_HALFPI;
        s1 = (d == 1984) ? -1.0f : 1.0f;
        c2 = -1.0f;
        s2 = SIN_NEGPI;
    } else {
        int i = (d >> 6) + 1;
        int j = d & 63;
        __sincosf(fmaf((float)i, STEP, NPI2), &s1, &c1);
        if (j == 0)       { c2 = -1.0f;       s2 = SIN_NEGPI; }
        else if (j == 16) { c2 = COS_HALFPI;  s2 = -1.0f; }
        else if (j == 48) { c2 = COS_HALFPI;  s2 = 1.0f; }
        else              { __sincosf(fmaf((float)j, STEP, NPI), &s2, &c2); }
    }
    const float dx = c1 * c2;
    const float dy = c1 * s2;
    const float dz = s1;

    if (blockIdx.y == 0) {
        out[OFF_DIRS + 3 * d + 0] = dx;
        out[OFF_DIRS + 3 * d + 1] = dy;
        out[OFF_DIRS + 3 * d + 2] = dz;
    }

    const float p = __ldg(&smooth[bp]);

    // ---- pass 1: zmax ----
    float zmax = 0.0f;
    #pragma unroll 8
    for (int v = 0; v < NV; v++) {
        float4 lv = slv[v];
        float z = fmaf(lv.x, dx, fmaf(lv.y, dy, lv.z * dz));
        zmax = fmaxf(zmax, z);
    }

    // ---- scale factor k (matches reference underflow guard) ----
    float zlog = log10f(zmax);                  // -inf if zmax == 0
    float expo = zlog * p;
    float lk   = (expo < -20.0f) ? ((-20.0f - expo) / p) : 0.0f;
    float kexp = fminf(fmaxf(ceilf(lk), 0.0f), 20.0f);   // +inf -> 20
    const float k = c_pow10[(int)kexp];

    // ---- pass 2 (fused): sum of clipped zms^p, and Sum w*lv ----
    const float pm1 = p - 1.0f;
    float sum = 0.0f, wx = 0.0f, wy = 0.0f, wz = 0.0f;
    #pragma unroll 8
    for (int v = 0; v < NV; v++) {
        float4 lv = slv[v];
        float z   = fmaf(lv.x, dx, fmaf(lv.y, dy, lv.z * dz));
        float zm  = fmaxf(z, 0.0f);
        float zms = zm * k;
        float l   = __log2f(zms);               // -inf when zms == 0
        float w   = exp2f(pm1 * l);             // zms^(p-1); 0 for zms==0
        float zp  = fminf(fmaxf(w * zms, 1e-20f), 1e20f);
        sum += (zms > 0.0f) ? zp : 0.0f;
        wx = fmaf(w, lv.x, wx);
        wy = fmaf(w, lv.y, wy);
        wz = fmaf(w, lv.z, wz);
    }

    // ---- h and scale ----
    float h, scale;
    if (zmax > 0.0f) {
        h = exp2f(__log2f(sum) * (1.0f / p));
        h = fminf(fmaxf(h, 1e-20f), 1e20f);
        scale = exp2f((1.0f - p) * __log2f(h));  // h^(1-p); bounded < 1e20
    } else {
        h = 1e-20f;                              // clip(0^(1/p))
        scale = 0.0f;
        wx = wy = wz = 0.0f;
    }

    // ---- outputs ----
    size_t pidx = ((size_t)bp * NDIR + d) * 3;
    out[OFF_POINTS + pidx + 0] = fmaf(wx, scale, mx);
    out[OFF_POINTS + pidx + 1] = fmaf(wy, scale, my);
    out[OFF_POINTS + pidx + 2] = fmaf(wz, scale, mz);

    float hout = h / k;
    ((float4*)(out + OFF_DH))[(size_t)bp * NDIR + d] =
        make_float4(dx, dy, dz, hout);
}

// ---------------------------------------------------------------------------
extern "C" void kernel_launch(void* const* d_in, const int* in_sizes, int n_in,
                              void* d_out, int out_size) {
    const float* verts  = (const float*)d_in[0];
    const float* smooth = (const float*)d_in[1];
    float* out = (float*)d_out;

    fused_kernel<<<dim3(NCHUNK, NBP), TPB>>>(verts, smooth, out);
}

// round 7
// speedup vs baseline: 1.4542x; 1.0875x over previous
#include <cuda_runtime.h>
#include <math.h>
#include <float.h>

// Problem geometry
#define NDIR   1986
#define NV     64
#define NBP    128     // B*P = 8*16
#define TPB    128
#define NCH    8       // 8 blocks x 256 dirs (2 per thread) = 2048 >= 1986

// Output layout (float element offsets inside d_out)
#define OFF_POINTS 0
#define OFF_DH     762624
#define OFF_OVER   1779456
#define OFF_MEAN   1779584
#define OFF_DIRS   1779968
#define OFF_LV     1785926

__constant__ float c_pow10[21] = {
    1e0f, 1e1f, 1e2f, 1e3f, 1e4f, 1e5f, 1e6f, 1e7f, 1e8f, 1e9f, 1e10f,
    1e11f, 1e12f, 1e13f, 1e14f, 1e15f, 1e16f, 1e17f, 1e18f, 1e19f, 1e20f
};

// f64->f32-cast trig at cancellation angles
#define COS_HALFPI  6.123234e-17f
#define SIN_NEGPI  -1.2246468e-16f

__device__ __forceinline__ void make_dir(int d, float& dx, float& dy, float& dz) {
    const float STEP = 0.09817477042468103f;   // pi/32
    const float NPI  = -3.14159265358979323846f;
    const float NPI2 = -1.57079632679489662f;
    float c1, s1, c2, s2;
    if (d >= 1984) {
        c1 = COS_HALFPI;
        s1 = (d == 1984) ? -1.0f : 1.0f;
        c2 = -1.0f;
        s2 = SIN_NEGPI;
    } else {
        int i = (d >> 6) + 1;
        int j = d & 63;
        __sincosf(fmaf((float)i, STEP, NPI2), &s1, &c1);
        if (j == 0)       { c2 = -1.0f;       s2 = SIN_NEGPI; }
        else if (j == 16) { c2 = COS_HALFPI;  s2 = -1.0f; }
        else if (j == 48) { c2 = COS_HALFPI;  s2 = 1.0f; }
        else              { __sincosf(fmaf((float)j, STEP, NPI), &s2, &c2); }
    }
    dx = c1 * c2;
    dy = c1 * s2;
    dz = s1;
}

// ---------------------------------------------------------------------------
// Fused kernel: grid (NCH, NBP), 128 threads; each thread owns 2 directions
// (d0 = bx*256 + tid, d1 = d0 + 128) so every LDS of local_v is reused twice.
// ---------------------------------------------------------------------------
__global__ __launch_bounds__(TPB)
void fused_kernel(const float* __restrict__ verts,
                  const float* __restrict__ smooth,
                  float* __restrict__ out) {
    __shared__ float4 slv[NV];
    __shared__ float  sred[6];
    __shared__ float  smean[3];

    const int bp  = blockIdx.y;
    const int tid = threadIdx.x;
    const int d0  = blockIdx.x * (2 * TPB) + tid;
    const int d1  = d0 + TPB;

    // ---- prologue: mean + local_v ----
    float px = 0.f, py = 0.f, pz = 0.f;
    if (tid < NV) {
        const float* vp = verts + (bp * NV + tid) * 3;
        px = vp[0]; py = vp[1]; pz = vp[2];
    }
    {
        float sx = px, sy = py, sz = pz;
        #pragma unroll
        for (int o = 16; o > 0; o >>= 1) {
            sx += __shfl_down_sync(0xffffffffu, sx, o);
            sy += __shfl_down_sync(0xffffffffu, sy, o);
            sz += __shfl_down_sync(0xffffffffu, sz, o);
        }
        int warp = tid >> 5, lane = tid & 31;
        if (warp < 2 && lane == 0) {
            sred[warp * 3 + 0] = sx;
            sred[warp * 3 + 1] = sy;
            sred[warp * 3 + 2] = sz;
        }
    }
    __syncthreads();
    if (tid == 0) {
        smean[0] = (sred[0] + sred[3]) * (1.0f / 64.0f);
        smean[1] = (sred[1] + sred[4]) * (1.0f / 64.0f);
        smean[2] = (sred[2] + sred[5]) * (1.0f / 64.0f);
    }
    __syncthreads();
    const float mx = smean[0], my = smean[1], mz = smean[2];
    if (tid < NV) {
        slv[tid] = make_float4(px - mx, py - my, pz - mz, 0.0f);
    }
    __syncthreads();

    // ---- aux per-bp outputs ----
    if (blockIdx.x == 0) {
        if (tid == 0) {
            out[OFF_MEAN + bp * 3 + 0] = mx;
            out[OFF_MEAN + bp * 3 + 1] = my;
            out[OFF_MEAN + bp * 3 + 2] = mz;
            out[OFF_OVER + bp] = 0.0f;
        }
        if (tid < NV) {
            float4 lv = slv[tid];
            int idx = OFF_LV + (bp * NV + tid) * 3;
            out[idx + 0] = lv.x;
            out[idx + 1] = lv.y;
            out[idx + 2] = lv.z;
        }
    }

    // ---- directions (d0 always valid; d1 may be tail) ----
    float ax, ay, az, bx, by, bz;
    make_dir(d0, ax, ay, az);
    make_dir(d1 < NDIR ? d1 : 0, bx, by, bz);
    const bool has1 = (d1 < NDIR);

    if (blockIdx.y == 0) {
        out[OFF_DIRS + 3 * d0 + 0] = ax;
        out[OFF_DIRS + 3 * d0 + 1] = ay;
        out[OFF_DIRS + 3 * d0 + 2] = az;
        if (has1) {
            out[OFF_DIRS + 3 * d1 + 0] = bx;
            out[OFF_DIRS + 3 * d1 + 1] = by;
            out[OFF_DIRS + 3 * d1 + 2] = bz;
        }
    }

    const float p   = __ldg(&smooth[bp]);
    const float pm1 = p - 1.0f;

    // ---- pass 1: raw-z max for both directions ----
    float zr0 = -FLT_MAX, zr1 = -FLT_MAX;
    #pragma unroll 16
    for (int v = 0; v < NV; v++) {
        float4 lv = slv[v];
        float z0 = fmaf(lv.x, ax, fmaf(lv.y, ay, lv.z * az));
        float z1 = fmaf(lv.x, bx, fmaf(lv.y, by, lv.z * bz));
        zr0 = fmaxf(zr0, z0);
        zr1 = fmaxf(zr1, z1);
    }
    const float zmax0 = fmaxf(zr0, 0.0f);
    const float zmax1 = fmaxf(zr1, 0.0f);

    // ---- scale factors ----
    float e0 = log10f(zmax0) * p;               // -inf*p if zmax==0
    float e1 = log10f(zmax1) * p;
    float lk0 = (e0 < -20.0f) ? ((-20.0f - e0) / p) : 0.0f;
    float lk1 = (e1 < -20.0f) ? ((-20.0f - e1) / p) : 0.0f;
    float ke0 = fminf(fmaxf(ceilf(lk0), 0.0f), 20.0f);
    float ke1 = fminf(fmaxf(ceilf(lk1), 0.0f), 20.0f);
    const float k0 = c_pow10[(int)ke0];
    const float k1 = c_pow10[(int)ke1];

    // ---- pass 2 (fused): sums + weighted vertex sums, both dirs ----
    float s0 = 0.f, wx0 = 0.f, wy0 = 0.f, wz0 = 0.f;
    float s1 = 0.f, wx1 = 0.f, wy1 = 0.f, wz1 = 0.f;
    #pragma unroll 8
    for (int v = 0; v < NV; v++) {
        float4 lv = slv[v];
        {
            float z   = fmaf(lv.x, ax, fmaf(lv.y, ay, lv.z * az));
            float zms = fmaxf(z, 0.0f) * k0;
            float l   = __log2f(zms);
            float w   = exp2f(pm1 * l);         // 0 when zms==0
            float zp  = fmaxf(w * zms, 1e-20f);
            s0 += (z > 0.0f) ? zp : 0.0f;
            wx0 = fmaf(w, lv.x, wx0);
            wy0 = fmaf(w, lv.y, wy0);
            wz0 = fmaf(w, lv.z, wz0);
        }
        {
            float z   = fmaf(lv.x, bx, fmaf(lv.y, by, lv.z * bz));
            float zms = fmaxf(z, 0.0f) * k1;
            float l   = __log2f(zms);
            float w   = exp2f(pm1 * l);
            float zp  = fmaxf(w * zms, 1e-20f);
            s1 += (z > 0.0f) ? zp : 0.0f;
            wx1 = fmaf(w, lv.x, wx1);
            wy1 = fmaf(w, lv.y, wy1);
            wz1 = fmaf(w, lv.z, wz1);
        }
    }

    // ---- epilogue helper ----
    const float invp = 1.0f / p;
    const float omp  = 1.0f - p;

    // dir 0
    {
        float h, scale;
        if (zmax0 > 0.0f) {
            h = exp2f(__log2f(s0) * invp);
            h = fminf(fmaxf(h, 1e-20f), 1e20f);
            scale = exp2f(omp * __log2f(h));
        } else {
            h = 1e-20f; scale = 0.0f; wx0 = wy0 = wz0 = 0.0f;
        }
        size_t pidx = ((size_t)bp * NDIR + d0) * 3;
        out[OFF_POINTS + pidx + 0] = fmaf(wx0, scale, mx);
        out[OFF_POINTS + pidx + 1] = fmaf(wy0, scale, my);
        out[OFF_POINTS + pidx + 2] = fmaf(wz0, scale, mz);
        ((float4*)(out + OFF_DH))[(size_t)bp * NDIR + d0] =
            make_float4(ax, ay, az, h / k0);
    }
    // dir 1
    if (has1) {
        float h, scale;
        if (zmax1 > 0.0f) {
            h = exp2f(__log2f(s1) * invp);
            h = fminf(fmaxf(h, 1e-20f), 1e20f);
            scale = exp2f(omp * __log2f(h));
        } else {
            h = 1e-20f; scale = 0.0f; wx1 = wy1 = wz1 = 0.0f;
        }
        size_t pidx = ((size_t)bp * NDIR + d1) * 3;
        out[OFF_POINTS + pidx + 0] = fmaf(wx1, scale, mx);
        out[OFF_POINTS + pidx + 1] = fmaf(wy1, scale, my);
        out[OFF_POINTS + pidx + 2] = fmaf(wz1, scale, mz);
        ((float4*)(out + OFF_DH))[(size_t)bp * NDIR + d1] =
            make_float4(bx, by, bz, h / k1);
    }
}

// ---------------------------------------------------------------------------
extern "C" void kernel_launch(void* const* d_in, const int* in_sizes, int n_in,
                              void* d_out, int out_size) {
    const float* verts  = (const float*)d_in[0];
    const float* smooth = (const float*)d_in[1];
    float* out = (float*)d_out;

    fused_kernel<<<dim3(NCH, NBP), TPB>>>(verts, smooth, out);
}